// round 1
// baseline (speedup 1.0000x reference)
#include <cuda_runtime.h>
#include <cuda_bf16.h>
#include <cstdint>

#define Hh 320
#define Ww 320
#define HWp 102400
#define Bb 8
#define NBLK 64

// ---------------- scratch (device globals: no allocation allowed) ----------------
__device__ float g_t1[(size_t)Bb*32*HWp];     // 32-ch temp (g1 out, then f1 out)
__device__ float g_t2[(size_t)Bb*8*HWp];      // 8-ch temp  (g2 out, then oa1 out)
__device__ float g_guid[(size_t)Bb*8*HWp];    // g3 out
__device__ float g_fus[(size_t)Bb*HWp];       // fusion
__device__ float g_t5[(size_t)Bb*24*HWp];     // oa2 out
__device__ float g_oa[(size_t)Bb*24*HWp];     // oa3 out
__device__ float g_part[32*NBLK*2];
__device__ float g_ss[64];                    // scale[C], shift[C]
__device__ float g_pool[Bb*32];
__device__ float g_gk[Bb*8];

// ---------------- packed f32x2 helpers ----------------
__device__ __forceinline__ unsigned long long dup2(float w) {
    unsigned long long r; asm("mov.b64 %0,{%1,%1};" : "=l"(r) : "f"(w)); return r;
}
__device__ __forceinline__ unsigned long long pack2(float lo, float hi) {
    unsigned long long r; asm("mov.b64 %0,{%1,%2};" : "=l"(r) : "f"(lo), "f"(hi)); return r;
}
__device__ __forceinline__ void unpack2(unsigned long long v, float& lo, float& hi) {
    asm("mov.b64 {%0,%1},%2;" : "=f"(lo), "=f"(hi) : "l"(v));
}
__device__ __forceinline__ void ffma2(unsigned long long& d, unsigned long long a, unsigned long long b) {
    asm("fma.rn.f32x2 %0,%1,%2,%0;" : "+l"(d) : "l"(a), "l"(b));
}

// ---------------- direct conv, f32x2 inner loop ----------------
// Tile: 64 (x) x 32 (y). 256 threads: 32 x-pairs, 8 row-groups, 4 rows/thread (stride 8).
// Optional fused input transform: relu(x*scale[ci]+shift[ci]) (previous stage's BN+ReLU).
template<int KS, int CIN, int COUT, int CB, bool IN_BN, bool HAS_BIAS, bool TANH_OUT>
__global__ __launch_bounds__(256) void conv_k(
    const float* __restrict__ in, const float* __restrict__ wgt,
    const float* __restrict__ bias, const float* __restrict__ ss,
    float* __restrict__ out)
{
    constexpr int PAD = KS / 2;
    constexpr int TW = 64, TH = 32;
    constexpr int SW = TW + KS - 1;   // 68 (K=5) / 66 (K=3)  (even -> float2 aligned)
    constexpr int SH = TH + KS - 1;
    constexpr int NCHUNK = COUT / CB;

    __shared__ __align__(8) float stile[SH * SW];
    __shared__ unsigned long long wsm[CB * KS * KS];

    const int tid = threadIdx.x;
    const int px  = tid & 31;
    const int rg  = tid >> 5;
    const int x0  = px * 2;

    const int tileX = blockIdx.x * TW;
    const int tileY = blockIdx.y * TH;
    const int z = blockIdx.z;
    const int b = z / NCHUNK;
    const int coBase = (z % NCHUNK) * CB;

    unsigned long long acc[4][CB];
#pragma unroll
    for (int r = 0; r < 4; r++)
#pragma unroll
        for (int c = 0; c < CB; c++) acc[r][c] = 0ull;

    for (int ci = 0; ci < CIN; ci++) {
        // weights for this cin, duplicated {w,w}
        for (int i = tid; i < CB * KS * KS; i += 256) {
            int c = i / (KS * KS), t = i - c * (KS * KS);
            float wv = wgt[((size_t)(coBase + c) * CIN + ci) * (KS * KS) + t];
            wsm[i] = dup2(wv);
        }
        // input tile (with fused BN+ReLU of prior stage; zero padding AFTER activation)
        float sc = 0.f, sh = 0.f;
        if (IN_BN) { sc = ss[ci]; sh = ss[CIN + ci]; }
        const float* inp = in + ((size_t)(b * CIN + ci)) * HWp;
        for (int i = tid; i < SH * SW; i += 256) {
            int sy = i / SW, sx = i - sy * SW;
            int gy = tileY + sy - PAD, gx = tileX + sx - PAD;
            float v = 0.f;
            if (gy >= 0 && gy < Hh && gx >= 0 && gx < Ww) {
                v = inp[gy * Ww + gx];
                if (IN_BN) v = fmaxf(fmaf(v, sc, sh), 0.f);
            }
            stile[i] = v;
        }
        __syncthreads();

#pragma unroll
        for (int ky = 0; ky < KS; ky++) {
            float f[4][KS + 1];
#pragma unroll
            for (int r = 0; r < 4; r++) {
                int row = rg + r * 8 + ky;
                const float2* rp = (const float2*)&stile[row * SW + x0];
#pragma unroll
                for (int q = 0; q < (KS + 1) / 2; q++) {
                    float2 t = rp[q];
                    f[r][2 * q] = t.x; f[r][2 * q + 1] = t.y;
                }
            }
#pragma unroll
            for (int kx = 0; kx < KS; kx++) {
                unsigned long long v[4];
#pragma unroll
                for (int r = 0; r < 4; r++) v[r] = pack2(f[r][kx], f[r][kx + 1]);
#pragma unroll
                for (int c = 0; c < CB; c++) {
                    unsigned long long w2 = wsm[c * KS * KS + ky * KS + kx];
#pragma unroll
                    for (int r = 0; r < 4; r++) ffma2(acc[r][c], v[r], w2);
                }
            }
        }
        __syncthreads();
    }

    // epilogue
#pragma unroll
    for (int c = 0; c < CB; c++) {
        float bv = HAS_BIAS ? bias[coBase + c] : 0.f;
        float* op = out + ((size_t)(b * COUT + coBase + c)) * HWp;
#pragma unroll
        for (int r = 0; r < 4; r++) {
            float lo, hi; unpack2(acc[r][c], lo, hi);
            lo += bv; hi += bv;
            if (TANH_OUT) { lo = tanhf(lo); hi = tanhf(hi); }
            int oy = tileY + rg + r * 8;
            int ox = tileX + x0;
            op[oy * Ww + ox]     = lo;
            op[oy * Ww + ox + 1] = hi;
        }
    }
}

// ---------------- BN stats: per-channel partial sums (deterministic, no atomics) ----------------
__global__ void stats_k(const float* __restrict__ x, float* __restrict__ part, int C)
{
    const int c = blockIdx.x, blk = blockIdx.y, NB = gridDim.y;
    const int tid = threadIdx.x;
    float s = 0.f, q = 0.f;
    for (int b = 0; b < Bb; b++) {
        const float* p = x + ((size_t)(b * C + c)) * HWp;
        for (int i = blk * 256 + tid; i < HWp; i += NB * 256) {
            float v = p[i]; s += v; q += v * v;
        }
    }
    __shared__ float rs[256], rq[256];
    rs[tid] = s; rq[tid] = q; __syncthreads();
    for (int off = 128; off > 0; off >>= 1) {
        if (tid < off) { rs[tid] += rs[tid + off]; rq[tid] += rq[tid + off]; }
        __syncthreads();
    }
    if (tid == 0) {
        part[(c * NB + blk) * 2]     = rs[0];
        part[(c * NB + blk) * 2 + 1] = rq[0];
    }
}

__global__ void bnfin_k(const float* __restrict__ part, const float* __restrict__ gamma,
                        const float* __restrict__ beta, int C, float* __restrict__ ss)
{
    int c = threadIdx.x;
    if (c >= C) return;
    double s = 0.0, q = 0.0;
    for (int i = 0; i < NBLK; i++) {
        s += part[(c * NBLK + i) * 2];
        q += part[(c * NBLK + i) * 2 + 1];
    }
    const double N = (double)Bb * HWp;
    float mean = (float)(s / N);
    float var  = (float)(q / N) - mean * mean;
    float scl = gamma[c] * rsqrtf(var + 1e-5f);
    ss[c]     = scl;
    ss[C + c] = beta[c] - mean * scl;
}

// ---------------- global-average-pool of feat (for sigma CAM) ----------------
__global__ void pool_k(const float* __restrict__ feat, float* __restrict__ p)
{
    const int bc = blockIdx.x;               // 0..255 = b*32+c
    const int tid = threadIdx.x;
    const float* src = feat + (size_t)bc * HWp;
    float s = 0.f;
    for (int i = tid; i < HWp; i += 256) s += src[i];
    __shared__ float rs[256];
    rs[tid] = s; __syncthreads();
    for (int off = 128; off > 0; off >>= 1) {
        if (tid < off) rs[tid] += rs[tid + off];
        __syncthreads();
    }
    if (tid == 0) p[bc] = rs[0] * (1.f / (float)HWp);
}

// ---------------- sigma MLP + gaussian window ----------------
__device__ __forceinline__ float celu1(float x) { return x > 0.f ? x : expm1f(x); }

__global__ void mlp_k(const float* __restrict__ p,
                      const float* __restrict__ s1w, const float* __restrict__ s1b,
                      const float* __restrict__ s2w, const float* __restrict__ s2b,
                      const float* __restrict__ s3w, const float* __restrict__ s3b,
                      float* __restrict__ gk)
{
    int b = threadIdx.x;
    if (b >= Bb) return;
    float h1[16];
#pragma unroll
    for (int j = 0; j < 16; j++) {
        float a = s1b[j];
        for (int i = 0; i < 32; i++) a += p[b * 32 + i] * s1w[j * 32 + i];
        h1[j] = celu1(a);
    }
    float h2[16];
#pragma unroll
    for (int j = 0; j < 16; j++) {
        float a = s2b[j];
        for (int i = 0; i < 16; i++) a += h1[i] * s2w[j * 16 + i];
        h2[j] = celu1(a);
    }
    float sg = s3b[0];
    for (int i = 0; i < 16; i++) sg += h2[i] * s3w[i];
    sg = fmaxf(sg, 0.f) + 0.001f;   // sigma
    sg += 0.2f;                      // sigma + sigma_gamma
    float e = expf(-1.f / (2.f * sg * sg));
    float d = 2.f * e + 1.f;
    float e1 = e / d, e0 = 1.f / d;          // w1 = [e1, e0, e1]
    float w00 = e1 * e1, w01 = e1 * e0;
    // w2 (9) = [w00,w01,w00, w01,e0*e0,w01, w00,w01,w00]; drop center -> 8
    gk[b * 8 + 0] = w00; gk[b * 8 + 1] = w01; gk[b * 8 + 2] = w00; gk[b * 8 + 3] = w01;
    gk[b * 8 + 4] = w01; gk[b * 8 + 5] = w00; gk[b * 8 + 6] = w01; gk[b * 8 + 7] = w00;
}

// ---------------- final: affinity normalize + modulated deform conv 1x9 + abs ----------------
__device__ __forceinline__ float bilin(const float* __restrict__ img, float ys, float xs)
{
    float y0f = floorf(ys), x0f = floorf(xs);
    float wy1 = ys - y0f, wx1 = xs - x0f;
    float wy0 = 1.f - wy1, wx0 = 1.f - wx1;
    int y0 = (int)y0f, x0 = (int)x0f;
    float v00 = 0.f, v01 = 0.f, v10 = 0.f, v11 = 0.f;
    bool yi0 = (y0 >= 0) & (y0 < Hh);
    bool yi1 = (y0 + 1 >= 0) & (y0 + 1 < Hh);
    bool xi0 = (x0 >= 0) & (x0 < Ww);
    bool xi1 = (x0 + 1 >= 0) & (x0 + 1 < Ww);
    if (yi0 & xi0) v00 = img[y0 * Ww + x0];
    if (yi0 & xi1) v01 = img[y0 * Ww + x0 + 1];
    if (yi1 & xi0) v10 = img[(y0 + 1) * Ww + x0];
    if (yi1 & xi1) v11 = img[(y0 + 1) * Ww + x0 + 1];
    return wy0 * wx0 * v00 + wy0 * wx1 * v01 + wy1 * wx0 * v10 + wy1 * wx1 * v11;
}

__global__ void final_k(const float* __restrict__ oa, const float* __restrict__ fusion,
                        const float* __restrict__ gk, const float* __restrict__ ascale_p,
                        float* __restrict__ out)
{
    int idx = blockIdx.x * 256 + threadIdx.x;
    if (idx >= Bb * HWp) return;
    int b = idx / HWp;
    int p = idx - b * HWp;
    int y = p / Ww;
    int x = p - y * Ww;

    float inv_as = 1.f / (ascale_p[0] + 1e-5f);

    float o[24];
    const float* ob = oa + (size_t)b * 24 * HWp + p;
#pragma unroll
    for (int c = 0; c < 24; c++) o[c] = ob[(size_t)c * HWp];

    float aff[8]; float s = 0.f;
#pragma unroll
    for (int k = 0; k < 8; k++) {
        float a = tanhf(o[16 + k]) * inv_as + gk[b * 8 + k];
        aff[k] = a;
        s += fabsf(a);
    }
    s += 1e-5f;
    s = fmaxf(s, 1.f);
    float inv = 1.f / s;
    float suma = 0.f;
#pragma unroll
    for (int k = 0; k < 8; k++) { aff[k] *= inv; suma += aff[k]; }
    float aref = 1.f - suma;

    const float* img = fusion + (size_t)b * HWp;
    float res = 0.f;
#pragma unroll
    for (int j = 0; j < 9; j++) {
        float m, dy, dx;
        if (j == 4) { m = aref; dy = 0.f; dx = 0.f; }
        else {
            int k = (j < 4) ? j : j - 1;
            m = aff[k];
            dy = o[2 * k];
            dx = o[2 * k + 1];
        }
        float ys = (float)y + (float)(j / 3 - 1) + dy;
        float xs = (float)x + (float)(j % 3 - 1) + dx;
        res += m * bilin(img, ys, xs);
    }
    out[idx] = fabsf(res);
}

// ---------------- launch ----------------
extern "C" void kernel_launch(void* const* d_in, const int* in_sizes, int n_in,
                              void* d_out, int out_size)
{
    const float* feat    = (const float*)d_in[0];
    const float* g1_w    = (const float*)d_in[1];
    const float* g1_g    = (const float*)d_in[2];
    const float* g1_b    = (const float*)d_in[3];
    const float* g2_w    = (const float*)d_in[4];
    const float* g2_g    = (const float*)d_in[5];
    const float* g2_b    = (const float*)d_in[6];
    const float* g3_w    = (const float*)d_in[7];
    const float* g3_bias = (const float*)d_in[8];
    const float* f1_w    = (const float*)d_in[9];
    const float* f1_g    = (const float*)d_in[10];
    const float* f1_b    = (const float*)d_in[11];
    const float* f2_w    = (const float*)d_in[12];
    const float* f2_bias = (const float*)d_in[13];
    const float* s1_w    = (const float*)d_in[14];
    const float* s1_b    = (const float*)d_in[15];
    const float* s2_w    = (const float*)d_in[16];
    const float* s2_b    = (const float*)d_in[17];
    const float* s3_w    = (const float*)d_in[18];
    const float* s3_b    = (const float*)d_in[19];
    const float* oa1_w   = (const float*)d_in[20];
    const float* oa1_g   = (const float*)d_in[21];
    const float* oa1_b   = (const float*)d_in[22];
    const float* oa2_w   = (const float*)d_in[23];
    const float* oa2_g   = (const float*)d_in[24];
    const float* oa2_b   = (const float*)d_in[25];
    const float* oa3_w   = (const float*)d_in[26];
    const float* oa3_bias= (const float*)d_in[27];
    const float* ascale  = (const float*)d_in[28];

    float *t1, *t2, *guid, *fus, *t5, *oa, *part, *ss, *pool, *gk;
    cudaGetSymbolAddress((void**)&t1,   g_t1);
    cudaGetSymbolAddress((void**)&t2,   g_t2);
    cudaGetSymbolAddress((void**)&guid, g_guid);
    cudaGetSymbolAddress((void**)&fus,  g_fus);
    cudaGetSymbolAddress((void**)&t5,   g_t5);
    cudaGetSymbolAddress((void**)&oa,   g_oa);
    cudaGetSymbolAddress((void**)&part, g_part);
    cudaGetSymbolAddress((void**)&ss,   g_ss);
    cudaGetSymbolAddress((void**)&pool, g_pool);
    cudaGetSymbolAddress((void**)&gk,   g_gk);

    const dim3 blk(256);
    const dim3 gA(5, 10, Bb * 2);   // COUT 32 / CB 16  or 24 / 12
    const dim3 gB(5, 10, Bb);       // single chunk

    // guid branch
    conv_k<5,32,32,16,false,false,false><<<gA, blk>>>(feat, g1_w, nullptr, nullptr, t1);
    stats_k<<<dim3(32, NBLK), blk>>>(t1, part, 32);
    bnfin_k<<<1, 32>>>(part, g1_g, g1_b, 32, ss);
    conv_k<5,32,8,8,true,false,false><<<gB, blk>>>(t1, g2_w, nullptr, ss, t2);
    stats_k<<<dim3(8, NBLK), blk>>>(t2, part, 8);
    bnfin_k<<<1, 32>>>(part, g2_g, g2_b, 8, ss);
    conv_k<5,8,8,8,true,true,false><<<gB, blk>>>(t2, g3_w, g3_bias, ss, guid);

    // fuse branch (reuses t1)
    conv_k<3,32,32,16,false,false,false><<<gA, blk>>>(feat, f1_w, nullptr, nullptr, t1);
    stats_k<<<dim3(32, NBLK), blk>>>(t1, part, 32);
    bnfin_k<<<1, 32>>>(part, f1_g, f1_b, 32, ss);
    conv_k<3,32,1,1,true,true,true><<<gB, blk>>>(t1, f2_w, f2_bias, ss, fus);

    // sigma branch
    pool_k<<<Bb * 32, blk>>>(feat, pool);
    mlp_k<<<1, 32>>>(pool, s1_w, s1_b, s2_w, s2_b, s3_w, s3_b, gk);

    // off/aff branch (reuses t2)
    conv_k<5,8,8,8,false,false,false><<<gB, blk>>>(guid, oa1_w, nullptr, nullptr, t2);
    stats_k<<<dim3(8, NBLK), blk>>>(t2, part, 8);
    bnfin_k<<<1, 32>>>(part, oa1_g, oa1_b, 8, ss);
    conv_k<5,8,24,12,true,false,false><<<gA, blk>>>(t2, oa2_w, nullptr, ss, t5);
    stats_k<<<dim3(24, NBLK), blk>>>(t5, part, 24);
    bnfin_k<<<1, 32>>>(part, oa2_g, oa2_b, 24, ss);
    conv_k<5,24,24,12,true,true,false><<<gA, blk>>>(t5, oa3_w, oa3_bias, ss, oa);

    // deformable gather
    final_k<<<(Bb * HWp + 255) / 256, blk>>>(oa, fus, gk, ascale, (float*)d_out);
}

// round 2
// speedup vs baseline: 1.2112x; 1.2112x over previous
#include <cuda_runtime.h>
#include <cuda_bf16.h>
#include <cstdint>

#define Hh 320
#define Ww 320
#define HWp 102400
#define Bb 8
#define NBLK 64

// ---------------- scratch (device globals: no allocation allowed) ----------------
__device__ float g_t1[(size_t)Bb*32*HWp];     // 32-ch temp (g1 out, then f1 out)
__device__ float g_t2[(size_t)Bb*8*HWp];      // 8-ch temp  (g2 out, then oa1 out)
__device__ float g_guid[(size_t)Bb*8*HWp];    // g3 out
__device__ float g_fus[(size_t)Bb*HWp];       // fusion
__device__ float g_t5[(size_t)Bb*24*HWp];     // oa2 out
__device__ float g_oa[(size_t)Bb*24*HWp];     // oa3 out
__device__ float g_part[32*NBLK*2];
__device__ float g_ss[64];                    // scale[C], shift[C]
__device__ float g_pool[Bb*32];
__device__ float g_gk[Bb*8];

// ---------------- packed f32x2 helpers ----------------
__device__ __forceinline__ unsigned long long dup2(float w) {
    unsigned long long r; asm("mov.b64 %0,{%1,%1};" : "=l"(r) : "f"(w)); return r;
}
__device__ __forceinline__ void unpack2(unsigned long long v, float& lo, float& hi) {
    asm("mov.b64 {%0,%1},%2;" : "=f"(lo), "=f"(hi) : "l"(v));
}
__device__ __forceinline__ void ffma2(unsigned long long& d, unsigned long long a, unsigned long long b) {
    asm("fma.rn.f32x2 %0,%1,%2,%0;" : "+l"(d) : "l"(a), "l"(b));
}

// ---------------- direct conv, f32x2 inner loop, dual shifted smem tiles ----------------
// Tile: 64 (x) x 32 (y). 256 threads: 32 x-pairs, 8 row-groups, 4 rows/thread (stride 8).
// Two smem copies of the input tile: sB[i] = sA[i+1], so any horizontal pair
// (x0+kx, x0+kx+1) is one aligned LDS.64 (even kx -> sA, odd kx -> sB at off-1).
// Optional fused input transform: relu(x*scale[ci]+shift[ci]) (previous stage's BN+ReLU).
template<int KS, int CIN, int COUT, int CB, bool IN_BN, bool HAS_BIAS, bool TANH_OUT>
__global__ __launch_bounds__(256, 2) void conv_k(
    const float* __restrict__ in, const float* __restrict__ wgt,
    const float* __restrict__ bias, const float* __restrict__ ss,
    float* __restrict__ out)
{
    constexpr int PAD = KS / 2;
    constexpr int TW = 64, TH = 32;
    constexpr int SW = TW + KS - 1;   // 68 (K=5) / 66 (K=3) -> even, float2 aligned
    constexpr int SH = TH + KS - 1;
    constexpr int NCHUNK = COUT / CB;

    __shared__ __align__(8) float sA[SH * SW];
    __shared__ __align__(8) float sB[SH * SW];
    __shared__ unsigned long long wsm[CB * KS * KS];

    const int tid = threadIdx.x;
    const int px  = tid & 31;
    const int rg  = tid >> 5;
    const int x0  = px * 2;

    const int tileX = blockIdx.x * TW;
    const int tileY = blockIdx.y * TH;
    const int z = blockIdx.z;
    const int b = z / NCHUNK;
    const int coBase = (z % NCHUNK) * CB;

    unsigned long long acc[4][CB];
#pragma unroll
    for (int r = 0; r < 4; r++)
#pragma unroll
        for (int c = 0; c < CB; c++) acc[r][c] = 0ull;

    for (int ci = 0; ci < CIN; ci++) {
        // weights for this cin, duplicated {w,w}
        if (tid < CB * KS * KS) {
            int c = tid / (KS * KS), t = tid - c * (KS * KS);
            wsm[tid] = dup2(wgt[((size_t)(coBase + c) * CIN + ci) * (KS * KS) + t]);
        }
        // input tile (with fused BN+ReLU of prior stage; zero padding AFTER activation)
        float sc = 0.f, sh = 0.f;
        if (IN_BN) { sc = ss[ci]; sh = ss[CIN + ci]; }
        const float* inp = in + ((size_t)(b * CIN + ci)) * HWp;
#pragma unroll 2
        for (int i = tid; i < SH * SW; i += 256) {
            int sy = i / SW, sx = i - sy * SW;
            int gy = tileY + sy - PAD, gx = tileX + sx - PAD;
            float v = 0.f;
            if (gy >= 0 && gy < Hh && gx >= 0 && gx < Ww) {
                v = inp[gy * Ww + gx];
                if (IN_BN) v = fmaxf(fmaf(v, sc, sh), 0.f);
            }
            sA[i] = v;
            if (sx > 0) sB[i - 1] = v;
        }
        __syncthreads();

#pragma unroll
        for (int ky = 0; ky < KS; ky++) {
#pragma unroll
            for (int kx = 0; kx < KS; kx++) {
                unsigned long long v[4];
#pragma unroll
                for (int r = 0; r < 4; r++) {
                    int off = (rg + r * 8 + ky) * SW + x0 + kx;
                    v[r] = (kx & 1) ? *(const unsigned long long*)&sB[off - 1]
                                    : *(const unsigned long long*)&sA[off];
                }
#pragma unroll
                for (int c = 0; c < CB; c++) {
                    unsigned long long w2 = wsm[c * KS * KS + ky * KS + kx];
#pragma unroll
                    for (int r = 0; r < 4; r++) ffma2(acc[r][c], v[r], w2);
                }
            }
        }
        __syncthreads();
    }

    // epilogue
#pragma unroll
    for (int c = 0; c < CB; c++) {
        float bv = HAS_BIAS ? bias[coBase + c] : 0.f;
        float* op = out + ((size_t)(b * COUT + coBase + c)) * HWp;
#pragma unroll
        for (int r = 0; r < 4; r++) {
            float lo, hi; unpack2(acc[r][c], lo, hi);
            lo += bv; hi += bv;
            if (TANH_OUT) { lo = tanhf(lo); hi = tanhf(hi); }
            int oy = tileY + rg + r * 8;
            int ox = tileX + x0;
            op[oy * Ww + ox]     = lo;
            op[oy * Ww + ox + 1] = hi;
        }
    }
}

// ---------------- BN stats: per-channel partial sums (deterministic, no atomics) ----------------
__global__ void stats_k(const float* __restrict__ x, float* __restrict__ part, int C)
{
    const int c = blockIdx.x, blk = blockIdx.y, NB = gridDim.y;
    const int tid = threadIdx.x;
    float s = 0.f, q = 0.f;
    for (int b = 0; b < Bb; b++) {
        const float* p = x + ((size_t)(b * C + c)) * HWp;
        for (int i = blk * 256 + tid; i < HWp; i += NB * 256) {
            float v = p[i]; s += v; q += v * v;
        }
    }
    __shared__ float rs[256], rq[256];
    rs[tid] = s; rq[tid] = q; __syncthreads();
    for (int off = 128; off > 0; off >>= 1) {
        if (tid < off) { rs[tid] += rs[tid + off]; rq[tid] += rq[tid + off]; }
        __syncthreads();
    }
    if (tid == 0) {
        part[(c * NB + blk) * 2]     = rs[0];
        part[(c * NB + blk) * 2 + 1] = rq[0];
    }
}

__global__ void bnfin_k(const float* __restrict__ part, const float* __restrict__ gamma,
                        const float* __restrict__ beta, int C, float* __restrict__ ss)
{
    int c = threadIdx.x;
    if (c >= C) return;
    double s = 0.0, q = 0.0;
    for (int i = 0; i < NBLK; i++) {
        s += part[(c * NBLK + i) * 2];
        q += part[(c * NBLK + i) * 2 + 1];
    }
    const double N = (double)Bb * HWp;
    float mean = (float)(s / N);
    float var  = (float)(q / N) - mean * mean;
    float scl = gamma[c] * rsqrtf(var + 1e-5f);
    ss[c]     = scl;
    ss[C + c] = beta[c] - mean * scl;
}

// ---------------- global-average-pool of feat (for sigma CAM) ----------------
__global__ void pool_k(const float* __restrict__ feat, float* __restrict__ p)
{
    const int bc = blockIdx.x;               // 0..255 = b*32+c
    const int tid = threadIdx.x;
    const float* src = feat + (size_t)bc * HWp;
    float s = 0.f;
    for (int i = tid; i < HWp; i += 256) s += src[i];
    __shared__ float rs[256];
    rs[tid] = s; __syncthreads();
    for (int off = 128; off > 0; off >>= 1) {
        if (tid < off) rs[tid] += rs[tid + off];
        __syncthreads();
    }
    if (tid == 0) p[bc] = rs[0] * (1.f / (float)HWp);
}

// ---------------- sigma MLP + gaussian window ----------------
__device__ __forceinline__ float celu1(float x) { return x > 0.f ? x : expm1f(x); }

__global__ void mlp_k(const float* __restrict__ p,
                      const float* __restrict__ s1w, const float* __restrict__ s1b,
                      const float* __restrict__ s2w, const float* __restrict__ s2b,
                      const float* __restrict__ s3w, const float* __restrict__ s3b,
                      float* __restrict__ gk)
{
    int b = threadIdx.x;
    if (b >= Bb) return;
    float h1[16];
#pragma unroll
    for (int j = 0; j < 16; j++) {
        float a = s1b[j];
        for (int i = 0; i < 32; i++) a += p[b * 32 + i] * s1w[j * 32 + i];
        h1[j] = celu1(a);
    }
    float h2[16];
#pragma unroll
    for (int j = 0; j < 16; j++) {
        float a = s2b[j];
        for (int i = 0; i < 16; i++) a += h1[i] * s2w[j * 16 + i];
        h2[j] = celu1(a);
    }
    float sg = s3b[0];
    for (int i = 0; i < 16; i++) sg += h2[i] * s3w[i];
    sg = fmaxf(sg, 0.f) + 0.001f;   // sigma
    sg += 0.2f;                      // sigma + sigma_gamma
    float e = expf(-1.f / (2.f * sg * sg));
    float d = 2.f * e + 1.f;
    float e1 = e / d, e0 = 1.f / d;          // w1 = [e1, e0, e1]
    float w00 = e1 * e1, w01 = e1 * e0;
    gk[b * 8 + 0] = w00; gk[b * 8 + 1] = w01; gk[b * 8 + 2] = w00; gk[b * 8 + 3] = w01;
    gk[b * 8 + 4] = w01; gk[b * 8 + 5] = w00; gk[b * 8 + 6] = w01; gk[b * 8 + 7] = w00;
}

// ---------------- final: affinity normalize + modulated deform conv 1x9 + abs ----------------
__device__ __forceinline__ float bilin(const float* __restrict__ img, float ys, float xs)
{
    float y0f = floorf(ys), x0f = floorf(xs);
    float wy1 = ys - y0f, wx1 = xs - x0f;
    float wy0 = 1.f - wy1, wx0 = 1.f - wx1;
    int y0 = (int)y0f, x0 = (int)x0f;
    float v00 = 0.f, v01 = 0.f, v10 = 0.f, v11 = 0.f;
    bool yi0 = (y0 >= 0) & (y0 < Hh);
    bool yi1 = (y0 + 1 >= 0) & (y0 + 1 < Hh);
    bool xi0 = (x0 >= 0) & (x0 < Ww);
    bool xi1 = (x0 + 1 >= 0) & (x0 + 1 < Ww);
    if (yi0 & xi0) v00 = img[y0 * Ww + x0];
    if (yi0 & xi1) v01 = img[y0 * Ww + x0 + 1];
    if (yi1 & xi0) v10 = img[(y0 + 1) * Ww + x0];
    if (yi1 & xi1) v11 = img[(y0 + 1) * Ww + x0 + 1];
    return wy0 * wx0 * v00 + wy0 * wx1 * v01 + wy1 * wx0 * v10 + wy1 * wx1 * v11;
}

__global__ void final_k(const float* __restrict__ oa, const float* __restrict__ fusion,
                        const float* __restrict__ gk, const float* __restrict__ ascale_p,
                        float* __restrict__ out)
{
    int idx = blockIdx.x * 256 + threadIdx.x;
    if (idx >= Bb * HWp) return;
    int b = idx / HWp;
    int p = idx - b * HWp;
    int y = p / Ww;
    int x = p - y * Ww;

    float inv_as = 1.f / (ascale_p[0] + 1e-5f);

    float o[24];
    const float* ob = oa + (size_t)b * 24 * HWp + p;
#pragma unroll
    for (int c = 0; c < 24; c++) o[c] = ob[(size_t)c * HWp];

    float aff[8]; float s = 0.f;
#pragma unroll
    for (int k = 0; k < 8; k++) {
        float a = tanhf(o[16 + k]) * inv_as + gk[b * 8 + k];
        aff[k] = a;
        s += fabsf(a);
    }
    s += 1e-5f;
    s = fmaxf(s, 1.f);
    float inv = 1.f / s;
    float suma = 0.f;
#pragma unroll
    for (int k = 0; k < 8; k++) { aff[k] *= inv; suma += aff[k]; }
    float aref = 1.f - suma;

    const float* img = fusion + (size_t)b * HWp;
    float res = 0.f;
#pragma unroll
    for (int j = 0; j < 9; j++) {
        float m, dy, dx;
        if (j == 4) { m = aref; dy = 0.f; dx = 0.f; }
        else {
            int k = (j < 4) ? j : j - 1;
            m = aff[k];
            dy = o[2 * k];
            dx = o[2 * k + 1];
        }
        float ys = (float)y + (float)(j / 3 - 1) + dy;
        float xs = (float)x + (float)(j % 3 - 1) + dx;
        res += m * bilin(img, ys, xs);
    }
    out[idx] = fabsf(res);
}

// ---------------- launch ----------------
extern "C" void kernel_launch(void* const* d_in, const int* in_sizes, int n_in,
                              void* d_out, int out_size)
{
    const float* feat    = (const float*)d_in[0];
    const float* g1_w    = (const float*)d_in[1];
    const float* g1_g    = (const float*)d_in[2];
    const float* g1_b    = (const float*)d_in[3];
    const float* g2_w    = (const float*)d_in[4];
    const float* g2_g    = (const float*)d_in[5];
    const float* g2_b    = (const float*)d_in[6];
    const float* g3_w    = (const float*)d_in[7];
    const float* g3_bias = (const float*)d_in[8];
    const float* f1_w    = (const float*)d_in[9];
    const float* f1_g    = (const float*)d_in[10];
    const float* f1_b    = (const float*)d_in[11];
    const float* f2_w    = (const float*)d_in[12];
    const float* f2_bias = (const float*)d_in[13];
    const float* s1_w    = (const float*)d_in[14];
    const float* s1_b    = (const float*)d_in[15];
    const float* s2_w    = (const float*)d_in[16];
    const float* s2_b    = (const float*)d_in[17];
    const float* s3_w    = (const float*)d_in[18];
    const float* s3_b    = (const float*)d_in[19];
    const float* oa1_w   = (const float*)d_in[20];
    const float* oa1_g   = (const float*)d_in[21];
    const float* oa1_b   = (const float*)d_in[22];
    const float* oa2_w   = (const float*)d_in[23];
    const float* oa2_g   = (const float*)d_in[24];
    const float* oa2_b   = (const float*)d_in[25];
    const float* oa3_w   = (const float*)d_in[26];
    const float* oa3_bias= (const float*)d_in[27];
    const float* ascale  = (const float*)d_in[28];

    float *t1, *t2, *guid, *fus, *t5, *oa, *part, *ss, *pool, *gk;
    cudaGetSymbolAddress((void**)&t1,   g_t1);
    cudaGetSymbolAddress((void**)&t2,   g_t2);
    cudaGetSymbolAddress((void**)&guid, g_guid);
    cudaGetSymbolAddress((void**)&fus,  g_fus);
    cudaGetSymbolAddress((void**)&t5,   g_t5);
    cudaGetSymbolAddress((void**)&oa,   g_oa);
    cudaGetSymbolAddress((void**)&part, g_part);
    cudaGetSymbolAddress((void**)&ss,   g_ss);
    cudaGetSymbolAddress((void**)&pool, g_pool);
    cudaGetSymbolAddress((void**)&gk,   g_gk);

    const dim3 blk(256);
    const dim3 g32(5, 10, Bb * 4);   // COUT 32, CB 8 -> 4 chunks
    const dim3 g24(5, 10, Bb * 3);   // COUT 24, CB 8 -> 3 chunks
    const dim3 g8 (5, 10, Bb);       // single chunk

    // guid branch
    conv_k<5,32,32,8,false,false,false><<<g32, blk>>>(feat, g1_w, nullptr, nullptr, t1);
    stats_k<<<dim3(32, NBLK), blk>>>(t1, part, 32);
    bnfin_k<<<1, 32>>>(part, g1_g, g1_b, 32, ss);
    conv_k<5,32,8,8,true,false,false><<<g8, blk>>>(t1, g2_w, nullptr, ss, t2);
    stats_k<<<dim3(8, NBLK), blk>>>(t2, part, 8);
    bnfin_k<<<1, 32>>>(part, g2_g, g2_b, 8, ss);
    conv_k<5,8,8,8,true,true,false><<<g8, blk>>>(t2, g3_w, g3_bias, ss, guid);

    // fuse branch (reuses t1)
    conv_k<3,32,32,8,false,false,false><<<g32, blk>>>(feat, f1_w, nullptr, nullptr, t1);
    stats_k<<<dim3(32, NBLK), blk>>>(t1, part, 32);
    bnfin_k<<<1, 32>>>(part, f1_g, f1_b, 32, ss);
    conv_k<3,32,1,1,true,true,true><<<g8, blk>>>(t1, f2_w, f2_bias, ss, fus);

    // sigma branch
    pool_k<<<Bb * 32, blk>>>(feat, pool);
    mlp_k<<<1, 32>>>(pool, s1_w, s1_b, s2_w, s2_b, s3_w, s3_b, gk);

    // off/aff branch (reuses t2)
    conv_k<5,8,8,8,false,false,false><<<g8, blk>>>(guid, oa1_w, nullptr, nullptr, t2);
    stats_k<<<dim3(8, NBLK), blk>>>(t2, part, 8);
    bnfin_k<<<1, 32>>>(part, oa1_g, oa1_b, 8, ss);
    conv_k<5,8,24,8,true,false,false><<<g24, blk>>>(t2, oa2_w, nullptr, ss, t5);
    stats_k<<<dim3(24, NBLK), blk>>>(t5, part, 24);
    bnfin_k<<<1, 32>>>(part, oa2_g, oa2_b, 24, ss);
    conv_k<5,24,24,8,true,true,false><<<g24, blk>>>(t5, oa3_w, oa3_bias, ss, oa);

    // deformable gather
    final_k<<<(Bb * HWp + 255) / 256, blk>>>(oa, fus, gk, ascale, (float*)d_out);
}